// round 14
// baseline (speedup 1.0000x reference)
#include <cuda_runtime.h>
#include <cuda_fp16.h>
#include <math.h>
#include <stdint.h>

#define NB 8192
#define NH 2048
#define NR 64

// fp16 scratch
__device__ __half g_hp16[NB * NH];
__device__ __half g_xt16[NB * NH];
__device__ __half g_ww16[NH * NH];
__device__ __half g_uw16[NH * NH];
__device__ __half g_wqkv16[3 * NR * NH];   // rows 0-63 WQ | 64-127 WK | 128-191 WV
__device__ __half g_wo16[NH * NR];
__device__ __half g_hth[NB * NH];          // h_t fp16 (k1 -> k234)

// sync: [0..160) k1 conversion counters; [160..288) qkv-partial flags;
//       [288..416) rv-ready flags
__device__ int g_sync[416];
// k234 pair-split scratch
__device__ float  g_qkvp[128 * 12288];     // per-panel fp32 qkv partial (48KB)
__device__ __half g_rvg[128 * 4096];       // per-panel swizzled rv block (8KB)

// ---------------------------------------------------------------------------
// helpers (sm_80-compatible; NO 'a'-suffix features)
// ---------------------------------------------------------------------------
__device__ __forceinline__ uint32_t smem_u32(const void* p) {
    uint32_t a;
    asm("{ .reg .u64 t; cvta.to.shared.u64 t, %1; cvt.u32.u64 %0, t; }"
        : "=r"(a) : "l"(p));
    return a;
}
#define LDMATRIX_X4(r, addr)                                                    \
    asm volatile("ldmatrix.sync.aligned.m8n8.x4.shared.b16 {%0,%1,%2,%3}, [%4];"\
        : "=r"((r)[0]), "=r"((r)[1]), "=r"((r)[2]), "=r"((r)[3]) : "r"(addr))

__device__ __forceinline__ void mma_f16(float c[4], const uint32_t a[4],
                                        uint32_t b0, uint32_t b1) {
    asm volatile(
        "mma.sync.aligned.m16n8k16.row.col.f32.f16.f16.f32 "
        "{%0,%1,%2,%3}, {%4,%5,%6,%7}, {%8,%9}, {%0,%1,%2,%3};"
        : "+f"(c[0]), "+f"(c[1]), "+f"(c[2]), "+f"(c[3])
        : "r"(a[0]), "r"(a[1]), "r"(a[2]), "r"(a[3]), "r"(b0), "r"(b1));
}

#define CP_ASYNC16(saddr, gptr)                                                \
    asm volatile("cp.async.cg.shared.global [%0], [%1], 16;"                   \
        :: "r"(saddr), "l"(gptr) : "memory")
#define CP_COMMIT() asm volatile("cp.async.commit_group;" ::: "memory")
#define CP_WAIT1()  asm volatile("cp.async.wait_group 1;" ::: "memory")
#define CP_WAIT0()  asm volatile("cp.async.wait_group 0;" ::: "memory")

__device__ __forceinline__ void sts_u16(uint32_t addr, uint16_t v) {
    asm volatile("st.shared.u16 [%0], %1;" :: "r"(addr), "h"(v));
}

// ---------------------------------------------------------------------------
// Kernel 1 (fp16 mma + fused fp32->fp16 conversion) — R12 version, frozen
// ---------------------------------------------------------------------------
#define K1_STAGE 32768
#define K1_SMEM (3 * K1_STAGE)

__global__ __launch_bounds__(256, 2)
void k1_liquid_f16(const float* __restrict__ h_prev,
                   const float* __restrict__ x_t,
                   const float* __restrict__ W_w,
                   const float* __restrict__ U_w,
                   const float* __restrict__ WQ,
                   const float* __restrict__ WK,
                   const float* __restrict__ WV,
                   const float* __restrict__ WO,
                   const float* __restrict__ U_b,
                   const float* __restrict__ alpha_raw,
                   float* __restrict__ h_t)
{
    extern __shared__ char sm[];
    const uint32_t sbase = smem_u32(sm);

    const int tid  = threadIdx.x;
    const int wid  = tid >> 5;
    const int lane = tid & 31;
    const int warp_m = wid & 1;
    const int warp_n = wid >> 1;
    const int bx = blockIdx.x;
    const int by = blockIdx.y;
    const int m0 = by * 128;
    const int n0 = bx * 128;

    // ================= conversion phase =================
    auto cvt_chunk = [&](const float* __restrict__ src, __half* dst, int f4base) {
#pragma unroll 4
        for (int i = 0; i < 16; ++i) {
            const int idx = f4base + tid + 256 * i;
            float4 v = ((const float4*)src)[idx];
            ((__half2*)dst)[2 * idx]     = __floats2half2_rn(v.x, v.y);
            ((__half2*)dst)[2 * idx + 1] = __floats2half2_rn(v.z, v.w);
        }
    };

    if (by == 0) {
        cvt_chunk(h_prev, g_hp16, 0 * 65536 + bx * 4096);
        cvt_chunk(h_prev, g_hp16, 1 * 65536 + bx * 4096);
        cvt_chunk(x_t,   g_xt16, 0 * 65536 + bx * 4096);
        cvt_chunk(x_t,   g_xt16, 1 * 65536 + bx * 4096);
    } else if (by <= 62) {
        cvt_chunk(h_prev, g_hp16, (by + 1) * 65536 + bx * 4096);
        cvt_chunk(x_t,   g_xt16, (by + 1) * 65536 + bx * 4096);
    }
    if (by >= 1 && by <= 16) {
        cvt_chunk(W_w, g_ww16, bx * 65536 + (by - 1) * 4096);
        cvt_chunk(U_w, g_uw16, bx * 65536 + (by - 1) * 4096);
    }
    if (by >= 17) {
        const int gidx = ((by - 17) * 16 + bx) * 256 + tid;
        if (gidx < 131072) {
            const float* src; __half* dst; int off;
            if (gidx < 32768)      { src = WQ; dst = g_wqkv16;            off = gidx; }
            else if (gidx < 65536) { src = WK; dst = g_wqkv16 + 64 * NH;  off = gidx - 32768; }
            else if (gidx < 98304) { src = WV; dst = g_wqkv16 + 128 * NH; off = gidx - 65536; }
            else                   { src = WO; dst = g_wo16;              off = gidx - 98304; }
            float4 v = ((const float4*)src)[off];
            ((__half2*)dst)[2 * off]     = __floats2half2_rn(v.x, v.y);
            ((__half2*)dst)[2 * off + 1] = __floats2half2_rn(v.z, v.w);
        }
    }
    __syncthreads();
    if (tid == 0) {
        __threadfence();
        if (by == 0) {
            atomicAdd(&g_sync[0], 1);  atomicAdd(&g_sync[1], 1);
            atomicAdd(&g_sync[64], 1); atomicAdd(&g_sync[65], 1);
        } else if (by <= 62) {
            atomicAdd(&g_sync[by + 1], 1);
            atomicAdd(&g_sync[64 + by + 1], 1);
        }
        if (by >= 1 && by <= 16) {
            atomicAdd(&g_sync[128 + bx], 1);
            atomicAdd(&g_sync[144 + bx], 1);
        }
        volatile int* c = g_sync;
        while (c[by] < 16 || c[64 + by] < 16 ||
               c[128 + bx] < 16 || c[144 + bx] < 16)
            __nanosleep(100);
    }
    __syncthreads();

    // ================= GEMM (R8 loop) =================
    auto load_stage = [&](int kt, int s) {
        const __half* Asrc = (kt < 32) ? g_hp16 : g_xt16;
        const __half* Bsrc = (kt < 32) ? g_ww16 : g_uw16;
        const int k0 = (kt & 31) << 6;
        const uint32_t sa = sbase + s * K1_STAGE;
        const uint32_t sb = sa + 16384;
#pragma unroll
        for (int i = 0; i < 4; ++i) {
            const int id = tid + 256 * i;
            const int row = id >> 3, c = id & 7;
            CP_ASYNC16(sa + row * 128 + ((c ^ (row & 7)) << 4),
                       Asrc + (size_t)(m0 + row) * NH + k0 + c * 8);
        }
#pragma unroll
        for (int i = 0; i < 4; ++i) {
            const int id = tid + 256 * i;
            const int row = id >> 3, c = id & 7;
            CP_ASYNC16(sb + row * 128 + ((c ^ (row & 7)) << 4),
                       Bsrc + (size_t)(n0 + row) * NH + k0 + c * 8);
        }
    };

    float acc[4][4][4];
#pragma unroll
    for (int a = 0; a < 4; ++a)
#pragma unroll
        for (int b = 0; b < 4; ++b)
#pragma unroll
            for (int d = 0; d < 4; ++d) acc[a][b][d] = 0.f;

    load_stage(0, 0); CP_COMMIT();
    load_stage(1, 1); CP_COMMIT();

    const int rl16 = lane & 15;
    const int ksel = lane >> 4;
    uint32_t aOff[4]; int aSwz[4];
    uint32_t bOff[2]; int bSwz[2];
#pragma unroll
    for (int mt = 0; mt < 4; ++mt) {
        const int r = warp_m * 64 + mt * 16 + rl16;
        aOff[mt] = r * 128; aSwz[mt] = r & 7;
    }
#pragma unroll
    for (int p = 0; p < 2; ++p) {
        const int r = warp_n * 32 + p * 16 + rl16;
        bOff[p] = 16384 + r * 128; bSwz[p] = r & 7;
    }

    for (int kt = 0; kt < 64; ++kt) {
        const int s = kt % 3;
        CP_WAIT1();
        __syncthreads();
        if (kt + 2 < 64) load_stage(kt + 2, (kt + 2) % 3);
        CP_COMMIT();

        const uint32_t stage = sbase + s * K1_STAGE;
#pragma unroll
        for (int ks = 0; ks < 4; ++ks) {
            const int chunk = ks * 2 + ksel;
            uint32_t a[4][4], b[2][4];
#pragma unroll
            for (int mt = 0; mt < 4; ++mt)
                LDMATRIX_X4(a[mt], stage + aOff[mt] + ((chunk ^ aSwz[mt]) << 4));
#pragma unroll
            for (int p = 0; p < 2; ++p)
                LDMATRIX_X4(b[p], stage + bOff[p] + ((chunk ^ bSwz[p]) << 4));
#pragma unroll
            for (int mt = 0; mt < 4; ++mt)
#pragma unroll
                for (int nt = 0; nt < 4; ++nt)
                    mma_f16(acc[mt][nt], a[mt],
                            b[nt >> 1][nt & 1], b[nt >> 1][2 + (nt & 1)]);
        }
    }

    const int g = lane >> 2, tig = lane & 3;
    const int mBase = m0 + warp_m * 64;
    const int nBase = n0 + warp_n * 32;
#pragma unroll
    for (int nt = 0; nt < 4; ++nt) {
        const int n = nBase + nt * 8 + tig * 2;
        const float om0 = 1.f / (1.f + __expf(alpha_raw[n]));
        const float om1 = 1.f / (1.f + __expf(alpha_raw[n + 1]));
        const float bi0 = U_b[n], bi1 = U_b[n + 1];
#pragma unroll
        for (int mt = 0; mt < 4; ++mt) {
            int m = mBase + mt * 16 + g;
            float2 hp = *(const float2*)(h_prev + (size_t)m * NH + n);
            float2 o;
            o.x = om0 * hp.x + tanhf(acc[mt][nt][0] + bi0);
            o.y = om1 * hp.y + tanhf(acc[mt][nt][1] + bi1);
            *(float2*)(h_t + (size_t)m * NH + n) = o;
            *(__half2*)(g_hth + (size_t)m * NH + n) = __floats2half2_rn(o.x, o.y);
            m += 8;
            hp = *(const float2*)(h_prev + (size_t)m * NH + n);
            o.x = om0 * hp.x + tanhf(acc[mt][nt][2] + bi0);
            o.y = om1 * hp.y + tanhf(acc[mt][nt][3] + bi1);
            *(float2*)(h_t + (size_t)m * NH + n) = o;
            *(__half2*)(g_hth + (size_t)m * NH + n) = __floats2half2_rn(o.x, o.y);
        }
    }
}

// ---------------------------------------------------------------------------
// Kernel 234 pair-split: per 64-row panel p, TWO CTAs (h = bid&1):
//   A) each computes qkv over half of K (16 kts); h0 publishes fp32 partial
//   B) h1 combines, softmax-routes, publishes swizzled rv block
//   C) h0 runs n-tiles 0..7, h1 runs 8..15 (disjoint y columns)
// grid 256 x 256 thr, occ 2 -> single wave.
// ---------------------------------------------------------------------------
#define K234_STAGE 32768                     // A 8KB + B 24KB
#define K234_SMEM  98304
#define QSTR 193
#define RV_OFF 53248
#define WO_OFF 61440

__global__ __launch_bounds__(256, 2)
void k234_fused(const float* __restrict__ x_t,
                const float* __restrict__ gamma,
                float* __restrict__ y)
{
    extern __shared__ char sm[];
    const uint32_t sbase = smem_u32(sm);
    float* smf = (float*)sm;

    const int tid  = threadIdx.x;
    const int wid  = tid >> 5;
    const int lane = tid & 31;
    const int p    = blockIdx.x >> 1;      // panel
    const int half = blockIdx.x & 1;       // 0 or 1
    const int m0   = p * 64;
    const unsigned full = 0xffffffffu;

    const int rl16 = lane & 15;
    const int ksel = lane >> 4;
    const int g    = lane >> 2;
    const int tig  = lane & 3;

    volatile int* flagA = g_sync + 160;    // [128]
    volatile int* flagR = g_sync + 288;    // [128]

    // ================= Phase A: QKV GEMM half (BM=64, BN=192, K=1024) ======
    {
        const int warp_m = wid & 1;
        const int warp_n = wid >> 1;
        const int klo = half * 16;

        auto load_stage = [&](int kt, int s) {
            const int k0 = kt << 6;
            const uint32_t sa = sbase + s * K234_STAGE;
            const uint32_t sb = sa + 8192;
#pragma unroll
            for (int i = 0; i < 2; ++i) {
                const int id = tid + 256 * i;
                const int row = id >> 3, c = id & 7;
                CP_ASYNC16(sa + row * 128 + ((c ^ (row & 7)) << 4),
                           g_hth + (size_t)(m0 + row) * NH + k0 + c * 8);
            }
#pragma unroll
            for (int i = 0; i < 6; ++i) {
                const int id = tid + 256 * i;
                const int row = id >> 3, c = id & 7;
                CP_ASYNC16(sb + row * 128 + ((c ^ (row & 7)) << 4),
                           g_wqkv16 + (size_t)row * NH + k0 + c * 8);
            }
        };

        float acc[2][6][4];
#pragma unroll
        for (int a = 0; a < 2; ++a)
#pragma unroll
            for (int b = 0; b < 6; ++b)
#pragma unroll
                for (int d = 0; d < 4; ++d) acc[a][b][d] = 0.f;

        load_stage(klo + 0, 0); CP_COMMIT();
        load_stage(klo + 1, 1); CP_COMMIT();

        uint32_t aOff[2]; int aSwz[2];
        uint32_t bOff[3]; int bSwz[3];
#pragma unroll
        for (int mt = 0; mt < 2; ++mt) {
            const int r = warp_m * 32 + mt * 16 + rl16;
            aOff[mt] = r * 128; aSwz[mt] = r & 7;
        }
#pragma unroll
        for (int q = 0; q < 3; ++q) {
            const int r = warp_n * 48 + q * 16 + rl16;
            bOff[q] = 8192 + r * 128; bSwz[q] = r & 7;
        }

        for (int it = 0; it < 16; ++it) {
            const int s = it % 3;
            CP_WAIT1();
            __syncthreads();
            if (it + 2 < 16) load_stage(klo + it + 2, (it + 2) % 3);
            CP_COMMIT();

            const uint32_t stage = sbase + s * K234_STAGE;
#pragma unroll
            for (int ks = 0; ks < 4; ++ks) {
                const int chunk = ks * 2 + ksel;
                uint32_t a[2][4], b[3][4];
#pragma unroll
                for (int mt = 0; mt < 2; ++mt)
                    LDMATRIX_X4(a[mt], stage + aOff[mt] + ((chunk ^ aSwz[mt]) << 4));
#pragma unroll
                for (int q = 0; q < 3; ++q)
                    LDMATRIX_X4(b[q], stage + bOff[q] + ((chunk ^ bSwz[q]) << 4));
#pragma unroll
                for (int mt = 0; mt < 2; ++mt)
#pragma unroll
                    for (int nt = 0; nt < 6; ++nt)
                        mma_f16(acc[mt][nt], a[mt],
                                b[nt >> 1][nt & 1], b[nt >> 1][2 + (nt & 1)]);
            }
        }
        CP_WAIT0();
        __syncthreads();

        if (half == 0) {
            // publish fp32 partial (coalesced [12][256] float4)
            float* pb = g_qkvp + (size_t)p * 12288;
#pragma unroll
            for (int a = 0; a < 2; ++a)
#pragma unroll
                for (int b = 0; b < 6; ++b)
                    *(float4*)(pb + ((a * 6 + b) * 256 + tid) * 4) =
                        make_float4(acc[a][b][0], acc[a][b][1],
                                    acc[a][b][2], acc[a][b][3]);
            __threadfence();
            __syncthreads();
            if (tid == 0) atomicExch((int*)&flagA[p], 1);
        } else {
            // combine with h0's partial
            if (tid == 0) { while (flagA[p] == 0) __nanosleep(100); }
            __syncthreads();
            __threadfence();
            const float* pb = g_qkvp + (size_t)p * 12288;
#pragma unroll
            for (int a = 0; a < 2; ++a)
#pragma unroll
                for (int b = 0; b < 6; ++b) {
                    float4 v = __ldcg((const float4*)(pb + ((a * 6 + b) * 256 + tid) * 4));
                    acc[a][b][0] += v.x; acc[a][b][1] += v.y;
                    acc[a][b][2] += v.z; acc[a][b][3] += v.w;
                }
            // write qkv fp32 to SMEM [64][QSTR]
            const int warp_m = wid & 1;
            const int warp_n = wid >> 1;
#pragma unroll
            for (int nt = 0; nt < 6; ++nt) {
                const int n = warp_n * 48 + nt * 8 + tig * 2;
#pragma unroll
                for (int mt = 0; mt < 2; ++mt) {
                    int m = warp_m * 32 + mt * 16 + g;
                    smf[m * QSTR + n]     = acc[mt][nt][0];
                    smf[m * QSTR + n + 1] = acc[mt][nt][1];
                    m += 8;
                    smf[m * QSTR + n]     = acc[mt][nt][2];
                    smf[m * QSTR + n + 1] = acc[mt][nt][3];
                }
            }
        }
    }
    __syncthreads();

    // ================= Phase B (h1 only): softmax + publish rv =============
    if (half == 1) {
#pragma unroll 1
        for (int rr = 0; rr < 8; ++rr) {
            const int r = wid * 8 + rr;
            const float* qk = smf + r * QSTR;
            const float q0s = 0.125f * qk[lane];
            const float q1s = 0.125f * qk[lane + 32];
            const float k0 = qk[64 + lane],  k1 = qk[96 + lane];
            const float v0 = qk[128 + lane], v1 = qk[160 + lane];

            float se0 = 0.f, sd0 = 0.f, se1 = 0.f, sd1 = 0.f;
#pragma unroll 8
            for (int j = 0; j < 32; ++j) {
                const float kj = __shfl_sync(full, k0, j);
                const float vj = __shfl_sync(full, v0, j);
                const float e0 = __expf(q0s * kj);
                const float e1 = __expf(q1s * kj);
                se0 += e0; sd0 = fmaf(e0, vj, sd0);
                se1 += e1; sd1 = fmaf(e1, vj, sd1);
            }
#pragma unroll 8
            for (int j = 0; j < 32; ++j) {
                const float kj = __shfl_sync(full, k1, j);
                const float vj = __shfl_sync(full, v1, j);
                const float e0 = __expf(q0s * kj);
                const float e1 = __expf(q1s * kj);
                se0 += e0; sd0 = fmaf(e0, vj, sd0);
                se1 += e1; sd1 = fmaf(e1, vj, sd1);
            }

            const int c0 = lane, c1 = lane + 32;
            sts_u16(sbase + RV_OFF + r * 128 +
                        (((c0 >> 3) ^ (r & 7)) << 4) + (c0 & 7) * 2,
                    __half_as_ushort(__float2half(sd0 / se0)));
            sts_u16(sbase + RV_OFF + r * 128 +
                        (((c1 >> 3) ^ (r & 7)) << 4) + (c1 & 7) * 2,
                    __half_as_ushort(__float2half(sd1 / se1)));
        }
        __syncthreads();
        // publish swizzled rv block (8KB) to global
        {
            const uint4* src = (const uint4*)(sm + RV_OFF);
            uint4* dst = (uint4*)(g_rvg + (size_t)p * 4096);
            dst[tid]       = src[tid];
            dst[tid + 256] = src[tid + 256];
        }
        __threadfence();
        __syncthreads();
        if (tid == 0) atomicExch((int*)&flagR[p], 1);
    } else {
        // h0: fetch rv block once ready
        if (tid == 0) { while (flagR[p] == 0) __nanosleep(100); }
        __syncthreads();
        __threadfence();
        {
            const __half* src = g_rvg + (size_t)p * 4096;
            CP_ASYNC16(sbase + RV_OFF + tid * 16,        src + tid * 8);
            CP_ASYNC16(sbase + RV_OFF + 4096 + tid * 16, src + 2048 + tid * 8);
            CP_COMMIT(); CP_WAIT0();
        }
        __syncthreads();
    }

    // ================= Phase C: y = gamma*(rv @ WO^T) + x_t (8 tiles) ======
    {
        const int warp_m = wid & 1;
        const int warp_n = wid >> 1;
        const float gm = gamma[0];
        const int tb = half * 8;

        uint32_t fa[2][4][4];
#pragma unroll
        for (int mt = 0; mt < 2; ++mt) {
            const int r = warp_m * 32 + mt * 16 + rl16;
#pragma unroll
            for (int ks = 0; ks < 4; ++ks) {
                const int chunk = ks * 2 + ksel;
                LDMATRIX_X4(fa[mt][ks],
                            sbase + RV_OFF + r * 128 + ((chunk ^ (r & 7)) << 4));
            }
        }

        auto load_wo = [&](int t, int buf) {
            const uint32_t sb = sbase + WO_OFF + buf * 16384;
#pragma unroll
            for (int i = 0; i < 4; ++i) {
                const int id = tid + 256 * i;
                const int row = id >> 3, c = id & 7;
                CP_ASYNC16(sb + row * 128 + ((c ^ (row & 7)) << 4),
                           g_wo16 + (size_t)(t * 128 + row) * NR + c * 8);
            }
        };

        load_wo(tb, 0); CP_COMMIT();

        for (int ti = 0; ti < 8; ++ti) {
            const int t = tb + ti;
            if (ti + 1 < 8) { load_wo(t + 1, (ti + 1) & 1); CP_COMMIT(); CP_WAIT1(); }
            else            { CP_WAIT0(); }
            __syncthreads();

            const uint32_t sb = sbase + WO_OFF + (ti & 1) * 16384;
            float acc[2][4][4];
#pragma unroll
            for (int a = 0; a < 2; ++a)
#pragma unroll
                for (int b = 0; b < 4; ++b)
#pragma unroll
                    for (int d = 0; d < 4; ++d) acc[a][b][d] = 0.f;

#pragma unroll
            for (int ks = 0; ks < 4; ++ks) {
                const int chunk = ks * 2 + ksel;
                uint32_t b[2][4];
#pragma unroll
                for (int q = 0; q < 2; ++q) {
                    const int r = warp_n * 32 + q * 16 + rl16;
                    LDMATRIX_X4(b[q], sb + r * 128 + ((chunk ^ (r & 7)) << 4));
                }
#pragma unroll
                for (int mt = 0; mt < 2; ++mt)
#pragma unroll
                    for (int nt = 0; nt < 4; ++nt)
                        mma_f16(acc[mt][nt], fa[mt][ks],
                                b[nt >> 1][nt & 1], b[nt >> 1][2 + (nt & 1)]);
            }

            const int nBase = t * 128 + warp_n * 32;
#pragma unroll
            for (int nt = 0; nt < 4; ++nt) {
                const int n = nBase + nt * 8 + tig * 2;
#pragma unroll
                for (int mt = 0; mt < 2; ++mt) {
                    int m = m0 + warp_m * 32 + mt * 16 + g;
                    float2 xv = *(const float2*)(x_t + (size_t)m * NH + n);
                    float2 o;
                    o.x = fmaf(gm, acc[mt][nt][0], xv.x);
                    o.y = fmaf(gm, acc[mt][nt][1], xv.y);
                    *(float2*)(y + (size_t)m * NH + n) = o;
                    m += 8;
                    xv = *(const float2*)(x_t + (size_t)m * NH + n);
                    o.x = fmaf(gm, acc[mt][nt][2], xv.x);
                    o.y = fmaf(gm, acc[mt][nt][3], xv.y);
                    *(float2*)(y + (size_t)m * NH + n) = o;
                }
            }
            __syncthreads();
        }
    }
}

// ---------------------------------------------------------------------------
extern "C" void kernel_launch(void* const* d_in, const int* in_sizes, int n_in,
                              void* d_out, int out_size)
{
    const float* h_prev    = (const float*)d_in[0];
    const float* x_t       = (const float*)d_in[1];
    const float* U_w       = (const float*)d_in[2];
    const float* U_b       = (const float*)d_in[3];
    const float* W_w       = (const float*)d_in[4];
    const float* alpha_raw = (const float*)d_in[5];
    const float* WQ        = (const float*)d_in[6];
    const float* WK        = (const float*)d_in[7];
    const float* WV        = (const float*)d_in[8];
    const float* WO        = (const float*)d_in[9];
    const float* gamma     = (const float*)d_in[10];

    float* h_t = (float*)d_out;
    float* y_t = h_t + (size_t)NB * NH;

    cudaFuncSetAttribute(k1_liquid_f16,
                         cudaFuncAttributeMaxDynamicSharedMemorySize, K1_SMEM);
    cudaFuncSetAttribute(k234_fused,
                         cudaFuncAttributeMaxDynamicSharedMemorySize, K234_SMEM);

    void* sync_addr = nullptr;
    cudaGetSymbolAddress(&sync_addr, g_sync);
    cudaMemsetAsync(sync_addr, 0, 416 * sizeof(int));

    dim3 g1(NH / 128, NB / 128);                      // (16, 64) = 1024 CTAs
    k1_liquid_f16<<<g1, 256, K1_SMEM>>>(h_prev, x_t, W_w, U_w,
                                        WQ, WK, WV, WO,
                                        U_b, alpha_raw, h_t);

    k234_fused<<<256, 256, K234_SMEM>>>(x_t, gamma, y_t);
}

// round 15
// speedup vs baseline: 1.5254x; 1.5254x over previous
#include <cuda_runtime.h>
#include <cuda_fp16.h>
#include <math.h>
#include <stdint.h>

#define NB 8192
#define NH 2048
#define NR 64

// fp16 scratch
__device__ __half g_hp16[NB * NH];
__device__ __half g_xt16[NB * NH];
__device__ __half g_ww16[NH * NH];
__device__ __half g_uw16[NH * NH];
__device__ __half g_wqkv16[3 * NR * NH];   // rows 0-63 WQ | 64-127 WK | 128-191 WV
__device__ __half g_wo16[NH * NR];
__device__ __half g_hth[NB * NH];          // h_t fp16 (k1 -> k234)

// conversion-completion counters: hp[0..64) xt[64..128) ww[128..144) uw[144..160)
__device__ int g_cnt[160];

// ---------------------------------------------------------------------------
// helpers (sm_80-compatible; NO 'a'-suffix features)
// ---------------------------------------------------------------------------
__device__ __forceinline__ uint32_t smem_u32(const void* p) {
    uint32_t a;
    asm("{ .reg .u64 t; cvta.to.shared.u64 t, %1; cvt.u32.u64 %0, t; }"
        : "=r"(a) : "l"(p));
    return a;
}
#define LDMATRIX_X4(r, addr)                                                    \
    asm volatile("ldmatrix.sync.aligned.m8n8.x4.shared.b16 {%0,%1,%2,%3}, [%4];"\
        : "=r"((r)[0]), "=r"((r)[1]), "=r"((r)[2]), "=r"((r)[3]) : "r"(addr))

__device__ __forceinline__ void mma_f16(float c[4], const uint32_t a[4],
                                        uint32_t b0, uint32_t b1) {
    asm volatile(
        "mma.sync.aligned.m16n8k16.row.col.f32.f16.f16.f32 "
        "{%0,%1,%2,%3}, {%4,%5,%6,%7}, {%8,%9}, {%0,%1,%2,%3};"
        : "+f"(c[0]), "+f"(c[1]), "+f"(c[2]), "+f"(c[3])
        : "r"(a[0]), "r"(a[1]), "r"(a[2]), "r"(a[3]), "r"(b0), "r"(b1));
}

#define CP_ASYNC16(saddr, gptr)                                                \
    asm volatile("cp.async.cg.shared.global [%0], [%1], 16;"                   \
        :: "r"(saddr), "l"(gptr) : "memory")
#define CP_COMMIT() asm volatile("cp.async.commit_group;" ::: "memory")
#define CP_WAIT1()  asm volatile("cp.async.wait_group 1;" ::: "memory")
#define CP_WAIT0()  asm volatile("cp.async.wait_group 0;" ::: "memory")

__device__ __forceinline__ void sts_u16(uint32_t addr, uint16_t v) {
    asm volatile("st.shared.u16 [%0], %1;" :: "r"(addr), "h"(v));
}

// ---------------------------------------------------------------------------
// Kernel 1 (fp16 mma + fused fp32->fp16 conversion) — R12 version, frozen
// ---------------------------------------------------------------------------
#define K1_STAGE 32768
#define K1_SMEM (3 * K1_STAGE)

__global__ __launch_bounds__(256, 2)
void k1_liquid_f16(const float* __restrict__ h_prev,
                   const float* __restrict__ x_t,
                   const float* __restrict__ W_w,
                   const float* __restrict__ U_w,
                   const float* __restrict__ WQ,
                   const float* __restrict__ WK,
                   const float* __restrict__ WV,
                   const float* __restrict__ WO,
                   const float* __restrict__ U_b,
                   const float* __restrict__ alpha_raw,
                   float* __restrict__ h_t)
{
    extern __shared__ char sm[];
    const uint32_t sbase = smem_u32(sm);

    const int tid  = threadIdx.x;
    const int wid  = tid >> 5;
    const int lane = tid & 31;
    const int warp_m = wid & 1;
    const int warp_n = wid >> 1;
    const int bx = blockIdx.x;
    const int by = blockIdx.y;
    const int m0 = by * 128;
    const int n0 = bx * 128;

    // ================= conversion phase =================
    auto cvt_chunk = [&](const float* __restrict__ src, __half* dst, int f4base) {
#pragma unroll 4
        for (int i = 0; i < 16; ++i) {
            const int idx = f4base + tid + 256 * i;
            float4 v = ((const float4*)src)[idx];
            ((__half2*)dst)[2 * idx]     = __floats2half2_rn(v.x, v.y);
            ((__half2*)dst)[2 * idx + 1] = __floats2half2_rn(v.z, v.w);
        }
    };

    if (by == 0) {
        cvt_chunk(h_prev, g_hp16, 0 * 65536 + bx * 4096);
        cvt_chunk(h_prev, g_hp16, 1 * 65536 + bx * 4096);
        cvt_chunk(x_t,   g_xt16, 0 * 65536 + bx * 4096);
        cvt_chunk(x_t,   g_xt16, 1 * 65536 + bx * 4096);
    } else if (by <= 62) {
        cvt_chunk(h_prev, g_hp16, (by + 1) * 65536 + bx * 4096);
        cvt_chunk(x_t,   g_xt16, (by + 1) * 65536 + bx * 4096);
    }
    if (by >= 1 && by <= 16) {
        cvt_chunk(W_w, g_ww16, bx * 65536 + (by - 1) * 4096);
        cvt_chunk(U_w, g_uw16, bx * 65536 + (by - 1) * 4096);
    }
    if (by >= 17) {
        const int gidx = ((by - 17) * 16 + bx) * 256 + tid;
        if (gidx < 131072) {
            const float* src; __half* dst; int off;
            if (gidx < 32768)      { src = WQ; dst = g_wqkv16;            off = gidx; }
            else if (gidx < 65536) { src = WK; dst = g_wqkv16 + 64 * NH;  off = gidx - 32768; }
            else if (gidx < 98304) { src = WV; dst = g_wqkv16 + 128 * NH; off = gidx - 65536; }
            else                   { src = WO; dst = g_wo16;              off = gidx - 98304; }
            float4 v = ((const float4*)src)[off];
            ((__half2*)dst)[2 * off]     = __floats2half2_rn(v.x, v.y);
            ((__half2*)dst)[2 * off + 1] = __floats2half2_rn(v.z, v.w);
        }
    }
    __syncthreads();
    if (tid == 0) {
        __threadfence();
        if (by == 0) {
            atomicAdd(&g_cnt[0], 1);  atomicAdd(&g_cnt[1], 1);
            atomicAdd(&g_cnt[64], 1); atomicAdd(&g_cnt[65], 1);
        } else if (by <= 62) {
            atomicAdd(&g_cnt[by + 1], 1);
            atomicAdd(&g_cnt[64 + by + 1], 1);
        }
        if (by >= 1 && by <= 16) {
            atomicAdd(&g_cnt[128 + bx], 1);
            atomicAdd(&g_cnt[144 + bx], 1);
        }
        volatile int* c = g_cnt;
        while (c[by] < 16 || c[64 + by] < 16 ||
               c[128 + bx] < 16 || c[144 + bx] < 16)
            __nanosleep(100);
    }
    __syncthreads();

    // ================= GEMM (R8 loop) =================
    auto load_stage = [&](int kt, int s) {
        const __half* Asrc = (kt < 32) ? g_hp16 : g_xt16;
        const __half* Bsrc = (kt < 32) ? g_ww16 : g_uw16;
        const int k0 = (kt & 31) << 6;
        const uint32_t sa = sbase + s * K1_STAGE;
        const uint32_t sb = sa + 16384;
#pragma unroll
        for (int i = 0; i < 4; ++i) {
            const int id = tid + 256 * i;
            const int row = id >> 3, c = id & 7;
            CP_ASYNC16(sa + row * 128 + ((c ^ (row & 7)) << 4),
                       Asrc + (size_t)(m0 + row) * NH + k0 + c * 8);
        }
#pragma unroll
        for (int i = 0; i < 4; ++i) {
            const int id = tid + 256 * i;
            const int row = id >> 3, c = id & 7;
            CP_ASYNC16(sb + row * 128 + ((c ^ (row & 7)) << 4),
                       Bsrc + (size_t)(n0 + row) * NH + k0 + c * 8);
        }
    };

    float acc[4][4][4];
#pragma unroll
    for (int a = 0; a < 4; ++a)
#pragma unroll
        for (int b = 0; b < 4; ++b)
#pragma unroll
            for (int d = 0; d < 4; ++d) acc[a][b][d] = 0.f;

    load_stage(0, 0); CP_COMMIT();
    load_stage(1, 1); CP_COMMIT();

    const int rl16 = lane & 15;
    const int ksel = lane >> 4;
    uint32_t aOff[4]; int aSwz[4];
    uint32_t bOff[2]; int bSwz[2];
#pragma unroll
    for (int mt = 0; mt < 4; ++mt) {
        const int r = warp_m * 64 + mt * 16 + rl16;
        aOff[mt] = r * 128; aSwz[mt] = r & 7;
    }
#pragma unroll
    for (int p = 0; p < 2; ++p) {
        const int r = warp_n * 32 + p * 16 + rl16;
        bOff[p] = 16384 + r * 128; bSwz[p] = r & 7;
    }

    for (int kt = 0; kt < 64; ++kt) {
        const int s = kt % 3;
        CP_WAIT1();
        __syncthreads();
        if (kt + 2 < 64) load_stage(kt + 2, (kt + 2) % 3);
        CP_COMMIT();

        const uint32_t stage = sbase + s * K1_STAGE;
#pragma unroll
        for (int ks = 0; ks < 4; ++ks) {
            const int chunk = ks * 2 + ksel;
            uint32_t a[4][4], b[2][4];
#pragma unroll
            for (int mt = 0; mt < 4; ++mt)
                LDMATRIX_X4(a[mt], stage + aOff[mt] + ((chunk ^ aSwz[mt]) << 4));
#pragma unroll
            for (int p = 0; p < 2; ++p)
                LDMATRIX_X4(b[p], stage + bOff[p] + ((chunk ^ bSwz[p]) << 4));
#pragma unroll
            for (int mt = 0; mt < 4; ++mt)
#pragma unroll
                for (int nt = 0; nt < 4; ++nt)
                    mma_f16(acc[mt][nt], a[mt],
                            b[nt >> 1][nt & 1], b[nt >> 1][2 + (nt & 1)]);
        }
    }

    const int g = lane >> 2, tig = lane & 3;
    const int mBase = m0 + warp_m * 64;
    const int nBase = n0 + warp_n * 32;
#pragma unroll
    for (int nt = 0; nt < 4; ++nt) {
        const int n = nBase + nt * 8 + tig * 2;
        const float om0 = 1.f / (1.f + __expf(alpha_raw[n]));
        const float om1 = 1.f / (1.f + __expf(alpha_raw[n + 1]));
        const float bi0 = U_b[n], bi1 = U_b[n + 1];
#pragma unroll
        for (int mt = 0; mt < 4; ++mt) {
            int m = mBase + mt * 16 + g;
            float2 hp = *(const float2*)(h_prev + (size_t)m * NH + n);
            float2 o;
            o.x = om0 * hp.x + tanhf(acc[mt][nt][0] + bi0);
            o.y = om1 * hp.y + tanhf(acc[mt][nt][1] + bi1);
            *(float2*)(h_t + (size_t)m * NH + n) = o;
            *(__half2*)(g_hth + (size_t)m * NH + n) = __floats2half2_rn(o.x, o.y);
            m += 8;
            hp = *(const float2*)(h_prev + (size_t)m * NH + n);
            o.x = om0 * hp.x + tanhf(acc[mt][nt][2] + bi0);
            o.y = om1 * hp.y + tanhf(acc[mt][nt][3] + bi1);
            *(float2*)(h_t + (size_t)m * NH + n) = o;
            *(__half2*)(g_hth + (size_t)m * NH + n) = __floats2half2_rn(o.x, o.y);
        }
    }
}

// ---------------------------------------------------------------------------
// Kernel 234 (fused, 32-row panels): 256 INDEPENDENT CTAs x 256 thr, occ 2.
// Each CTA: A) qkv = h_t[32 rows] @ [WQ;WK;WV]^T  (warp tile 16x48)
//           B) routed softmax (8 warps x 4 rows)
//           C) y = gamma*(rv @ WO^T) + x_t  (warp tile 16x32, 16 n-tiles)
// Two co-resident panels per SM overlap phase A (compute) with phase C
// (memory) naturally — no cross-CTA sync.
// SMEM: stages 3 x (A 4KB + B 24KB) = 84KB; B/C reuse region:
//   qkv fp32 [0,24704) stride 193; rv [24704,28800); WO bufs [28800,61568)
// ---------------------------------------------------------------------------
#define K234_STAGE 28672
#define K234_SMEM  86016
#define QSTR 193
#define RV_OFF 24704
#define WO_OFF 28800

__global__ __launch_bounds__(256, 2)
void k234_fused(const float* __restrict__ x_t,
                const float* __restrict__ gamma,
                float* __restrict__ y)
{
    extern __shared__ char sm[];
    const uint32_t sbase = smem_u32(sm);
    float* smf = (float*)sm;

    const int tid  = threadIdx.x;
    const int wid  = tid >> 5;
    const int lane = tid & 31;
    const int m0   = blockIdx.x * 32;
    const unsigned full = 0xffffffffu;

    const int rl16 = lane & 15;
    const int ksel = lane >> 4;
    const int g    = lane >> 2;
    const int tig  = lane & 3;
    const int warp_m = wid & 1;      // 2 x 16 rows
    const int warp_n = wid >> 1;     // A: 4 x 48 cols; C: 4 x 32 cols

    // ================= Phase A: QKV GEMM (BM=32, BN=192, K=2048) ===========
    {
        auto load_stage = [&](int kt, int s) {
            const int k0 = kt << 6;
            const uint32_t sa = sbase + s * K234_STAGE;
            const uint32_t sb = sa + 4096;
            {   // A: 256 chunks / 256 thr
                const int row = tid >> 3, c = tid & 7;
                CP_ASYNC16(sa + row * 128 + ((c ^ (row & 7)) << 4),
                           g_hth + (size_t)(m0 + row) * NH + k0 + c * 8);
            }
#pragma unroll
            for (int i = 0; i < 6; ++i) {        // B: 1536 chunks / 256 thr
                const int id = tid + 256 * i;
                const int row = id >> 3, c = id & 7;
                CP_ASYNC16(sb + row * 128 + ((c ^ (row & 7)) << 4),
                           g_wqkv16 + (size_t)row * NH + k0 + c * 8);
            }
        };

        float acc[6][4];
#pragma unroll
        for (int b = 0; b < 6; ++b)
#pragma unroll
            for (int d = 0; d < 4; ++d) acc[b][d] = 0.f;

        load_stage(0, 0); CP_COMMIT();
        load_stage(1, 1); CP_COMMIT();

        uint32_t aOff; int aSwz;
        uint32_t bOff[3]; int bSwz[3];
        {
            const int r = warp_m * 16 + rl16;
            aOff = r * 128; aSwz = r & 7;
        }
#pragma unroll
        for (int p = 0; p < 3; ++p) {
            const int r = warp_n * 48 + p * 16 + rl16;
            bOff[p] = 4096 + r * 128; bSwz[p] = r & 7;
        }

        for (int kt = 0; kt < 32; ++kt) {
            const int s = kt % 3;
            CP_WAIT1();
            __syncthreads();
            if (kt + 2 < 32) load_stage(kt + 2, (kt + 2) % 3);
            CP_COMMIT();

            const uint32_t stage = sbase + s * K234_STAGE;
#pragma unroll
            for (int ks = 0; ks < 4; ++ks) {
                const int chunk = ks * 2 + ksel;
                uint32_t a[4], b[3][4];
                LDMATRIX_X4(a, stage + aOff + ((chunk ^ aSwz) << 4));
#pragma unroll
                for (int p = 0; p < 3; ++p)
                    LDMATRIX_X4(b[p], stage + bOff[p] + ((chunk ^ bSwz[p]) << 4));
#pragma unroll
                for (int nt = 0; nt < 6; ++nt)
                    mma_f16(acc[nt], a,
                            b[nt >> 1][nt & 1], b[nt >> 1][2 + (nt & 1)]);
            }
        }

        CP_WAIT0();
        __syncthreads();

        // write qkv fp32 to SMEM [32][QSTR]
#pragma unroll
        for (int nt = 0; nt < 6; ++nt) {
            const int n = warp_n * 48 + nt * 8 + tig * 2;
            int m = warp_m * 16 + g;
            smf[m * QSTR + n]     = acc[nt][0];
            smf[m * QSTR + n + 1] = acc[nt][1];
            m += 8;
            smf[m * QSTR + n]     = acc[nt][2];
            smf[m * QSTR + n + 1] = acc[nt][3];
        }
    }
    __syncthreads();

    // ================= Phase B: softmax routing (8 warps x 4 rows) =========
    {
#pragma unroll 1
        for (int rr = 0; rr < 4; ++rr) {
            const int r = wid * 4 + rr;
            const float* qk = smf + r * QSTR;
            const float q0s = 0.125f * qk[lane];
            const float q1s = 0.125f * qk[lane + 32];
            const float k0 = qk[64 + lane],  k1 = qk[96 + lane];
            const float v0 = qk[128 + lane], v1 = qk[160 + lane];

            float se0 = 0.f, sd0 = 0.f, se1 = 0.f, sd1 = 0.f;
#pragma unroll 8
            for (int j = 0; j < 32; ++j) {
                const float kj = __shfl_sync(full, k0, j);
                const float vj = __shfl_sync(full, v0, j);
                const float e0 = __expf(q0s * kj);
                const float e1 = __expf(q1s * kj);
                se0 += e0; sd0 = fmaf(e0, vj, sd0);
                se1 += e1; sd1 = fmaf(e1, vj, sd1);
            }
#pragma unroll 8
            for (int j = 0; j < 32; ++j) {
                const float kj = __shfl_sync(full, k1, j);
                const float vj = __shfl_sync(full, v1, j);
                const float e0 = __expf(q0s * kj);
                const float e1 = __expf(q1s * kj);
                se0 += e0; sd0 = fmaf(e0, vj, sd0);
                se1 += e1; sd1 = fmaf(e1, vj, sd1);
            }

            const int c0 = lane, c1 = lane + 32;
            sts_u16(sbase + RV_OFF + r * 128 +
                        (((c0 >> 3) ^ (r & 7)) << 4) + (c0 & 7) * 2,
                    __half_as_ushort(__float2half(sd0 / se0)));
            sts_u16(sbase + RV_OFF + r * 128 +
                        (((c1 >> 3) ^ (r & 7)) << 4) + (c1 & 7) * 2,
                    __half_as_ushort(__float2half(sd1 / se1)));
        }
    }
    __syncthreads();

    // ================= Phase C: y = gamma*(rv @ WO^T) + x_t ================
    {
        const float gm = gamma[0];

        uint32_t fa[4][4];
        {
            const int r = warp_m * 16 + rl16;
#pragma unroll
            for (int ks = 0; ks < 4; ++ks) {
                const int chunk = ks * 2 + ksel;
                LDMATRIX_X4(fa[ks],
                            sbase + RV_OFF + r * 128 + ((chunk ^ (r & 7)) << 4));
            }
        }

        auto load_wo = [&](int t, int buf) {
            const uint32_t sb = sbase + WO_OFF + buf * 16384;
#pragma unroll
            for (int i = 0; i < 4; ++i) {        // 1024 chunks / 256 thr
                const int id = tid + 256 * i;
                const int row = id >> 3, c = id & 7;
                CP_ASYNC16(sb + row * 128 + ((c ^ (row & 7)) << 4),
                           g_wo16 + (size_t)(t * 128 + row) * NR + c * 8);
            }
        };

        load_wo(0, 0); CP_COMMIT();

        for (int t = 0; t < 16; ++t) {
            if (t + 1 < 16) { load_wo(t + 1, (t + 1) & 1); CP_COMMIT(); CP_WAIT1(); }
            else            { CP_WAIT0(); }
            __syncthreads();

            const uint32_t sb = sbase + WO_OFF + (t & 1) * 16384;
            float acc[4][4];
#pragma unroll
            for (int b = 0; b < 4; ++b)
#pragma unroll
                for (int d = 0; d < 4; ++d) acc[b][d] = 0.f;

#pragma unroll
            for (int ks = 0; ks < 4; ++ks) {
                const int chunk = ks * 2 + ksel;
                uint32_t b[2][4];
#pragma unroll
                for (int p = 0; p < 2; ++p) {
                    const int r = warp_n * 32 + p * 16 + rl16;
                    LDMATRIX_X4(b[p], sb + r * 128 + ((chunk ^ (r & 7)) << 4));
                }
#pragma unroll
                for (int nt = 0; nt < 4; ++nt)
                    mma_f16(acc[nt], fa[ks],
                            b[nt >> 1][nt & 1], b[nt >> 1][2 + (nt & 1)]);
            }

            const int nBase = t * 128 + warp_n * 32;
#pragma unroll
            for (int nt = 0; nt < 4; ++nt) {
                const int n = nBase + nt * 8 + tig * 2;
                int m = m0 + warp_m * 16 + g;
                float2 xv = *(const float2*)(x_t + (size_t)m * NH + n);
                float2 o;
                o.x = fmaf(gm, acc[nt][0], xv.x);
                o.y = fmaf(gm, acc[nt][1], xv.y);
                *(float2*)(y + (size_t)m * NH + n) = o;
                m += 8;
                xv = *(const float2*)(x_t + (size_t)m * NH + n);
                o.x = fmaf(gm, acc[nt][2], xv.x);
                o.y = fmaf(gm, acc[nt][3], xv.y);
                *(float2*)(y + (size_t)m * NH + n) = o;
            }
            __syncthreads();
        }
    }
}

// ---------------------------------------------------------------------------
extern "C" void kernel_launch(void* const* d_in, const int* in_sizes, int n_in,
                              void* d_out, int out_size)
{
    const float* h_prev    = (const float*)d_in[0];
    const float* x_t       = (const float*)d_in[1];
    const float* U_w       = (const float*)d_in[2];
    const float* U_b       = (const float*)d_in[3];
    const float* W_w       = (const float*)d_in[4];
    const float* alpha_raw = (const float*)d_in[5];
    const float* WQ        = (const float*)d_in[6];
    const float* WK        = (const float*)d_in[7];
    const float* WV        = (const float*)d_in[8];
    const float* WO        = (const float*)d_in[9];
    const float* gamma     = (const float*)d_in[10];

    float* h_t = (float*)d_out;
    float* y_t = h_t + (size_t)NB * NH;

    cudaFuncSetAttribute(k1_liquid_f16,
                         cudaFuncAttributeMaxDynamicSharedMemorySize, K1_SMEM);
    cudaFuncSetAttribute(k234_fused,
                         cudaFuncAttributeMaxDynamicSharedMemorySize, K234_SMEM);

    void* cnt_addr = nullptr;
    cudaGetSymbolAddress(&cnt_addr, g_cnt);
    cudaMemsetAsync(cnt_addr, 0, 160 * sizeof(int));

    dim3 g1(NH / 128, NB / 128);                      // (16, 64) = 1024 CTAs
    k1_liquid_f16<<<g1, 256, K1_SMEM>>>(h_prev, x_t, W_w, U_w,
                                        WQ, WK, WV, WO,
                                        U_b, alpha_raw, h_t);

    k234_fused<<<NB / 32, 256, K234_SMEM>>>(x_t, gamma, y_t);
}